// round 16
// baseline (speedup 1.0000x reference)
#include <cuda_runtime.h>
#include <cuda_fp16.h>
#include <cstdint>
#include <cstddef>

#define BSZ 16384
#define HSZ 1024

#define BM 128
#define BN 128
#define BK 32                         /* halves of K per tile */
#define NST 5
#define APADH 40                      /* halves per smem row = 80 B */
#define A_HALVES (BM * APADH)         /* 5120 */
#define B_HALVES (BN * APADH)         /* 5120 */
#define STAGE_HALVES (A_HALVES + B_HALVES)      /* 10240 -> 20480 B */
#define STAGE_BYTES (STAGE_HALVES * 2)
#define BIAS_BYTE_OFF (NST * STAGE_BYTES)       /* 102400 */
#define SMEM_BYTES (BIAS_BYTE_OFF + BN * 4)     /* 102912, x2 CTA = 205824 */

#define NTHREADS 256                  /* 8 warps, 64x32 warp tiles, 2 CTAs/SM */

// fp16 scratch
__device__ __align__(16) __half g_hr16[(size_t)BSZ * HSZ];    // h*r (fp16)
__device__ __align__(16) __half g_u16[(size_t)BSZ * HSZ];     // update gate (fp16)
__device__ __align__(16) __half g_gc16[(size_t)BSZ * HSZ];    // x@W^T + biases (fp16)
__device__ __align__(16) __half g_w16[6][(size_t)HSZ * HSZ];  // Wr,Ur,Wu,Uu,W,U

// readiness counters per m-block (128 blocks of 128 rows)
__device__ int g_ready0[BSZ / BM];    // gate-0 tiles stored (target 8)
__device__ int g_ready12[BSZ / BM];   // gate-1/2 tiles stored (target 16)

// ---------------- helpers (base-ISA only) ----------------
__device__ __forceinline__ void cp16(void* dst_smem, const void* src) {
    uint32_t d = (uint32_t)__cvta_generic_to_shared(dst_smem);
    asm volatile("cp.async.cg.shared.global [%0], [%1], 16;" :: "r"(d), "l"(src));
}
__device__ __forceinline__ void cp_commit() {
    asm volatile("cp.async.commit_group;" ::: "memory");
}
__device__ __forceinline__ void cp_wait(int pending) {
    if (pending >= 3)      asm volatile("cp.async.wait_group 3;" ::: "memory");
    else if (pending == 2) asm volatile("cp.async.wait_group 2;" ::: "memory");
    else if (pending == 1) asm volatile("cp.async.wait_group 1;" ::: "memory");
    else                   asm volatile("cp.async.wait_group 0;" ::: "memory");
}
__device__ __forceinline__ void mma_f16(float* c, const uint32_t* a, uint32_t b0, uint32_t b1) {
    asm volatile(
        "mma.sync.aligned.m16n8k16.row.col.f32.f16.f16.f32 "
        "{%0,%1,%2,%3}, {%4,%5,%6,%7}, {%8,%9}, {%0,%1,%2,%3};"
        : "+f"(c[0]), "+f"(c[1]), "+f"(c[2]), "+f"(c[3])
        : "r"(a[0]), "r"(a[1]), "r"(a[2]), "r"(a[3]), "r"(b0), "r"(b1));
}
__device__ __forceinline__ void ldsm4(uint32_t& r0, uint32_t& r1, uint32_t& r2, uint32_t& r3,
                                      uint32_t addr) {
    asm volatile("ldmatrix.sync.aligned.m8n8.x4.shared.b16 {%0,%1,%2,%3}, [%4];"
        : "=r"(r0), "=r"(r1), "=r"(r2), "=r"(r3) : "r"(addr));
}
__device__ __forceinline__ float sigmf(float x) { return 1.0f / (1.0f + __expf(-x)); }
__device__ __forceinline__ float tanhfast(float x) { return 2.0f / (1.0f + __expf(-2.0f * x)) - 1.0f; }

__device__ __forceinline__ uint2 pack4h(float4 v) {
    __half2 lo = __floats2half2_rn(v.x, v.y);
    __half2 hi = __floats2half2_rn(v.z, v.w);
    uint2 o;
    o.x = *(uint32_t*)&lo;
    o.y = *(uint32_t*)&hi;
    return o;
}

// ---------------- fp16 pre-convert: 6 weight matrices (+ counter reset) ----
__global__ void __launch_bounds__(256) cvt_w6(
    const float4* __restrict__ s0, const float4* __restrict__ s1,
    const float4* __restrict__ s2, const float4* __restrict__ s3,
    const float4* __restrict__ s4, const float4* __restrict__ s5)
{
    if (blockIdx.x == 0 && blockIdx.y == 0 && threadIdx.x < BSZ / BM) {
        g_ready0[threadIdx.x] = 0;
        g_ready12[threadIdx.x] = 0;
    }
    const int n4 = (HSZ * HSZ) / 4;
    int seg = blockIdx.y;
    const float4* src = (seg == 0) ? s0 : (seg == 1) ? s1 : (seg == 2) ? s2
                      : (seg == 3) ? s3 : (seg == 4) ? s4 : s5;
    uint2* dst = (uint2*)g_w16 + (size_t)seg * n4;
    int i = blockIdx.x * 256 + threadIdx.x;
    int stride = gridDim.x * 256;
    for (; i + stride < n4; i += 2 * stride) {
        float4 a = src[i];
        float4 b = src[i + stride];
        dst[i] = pack4h(a);
        dst[i + stride] = pack4h(b);
    }
    if (i < n4) dst[i] = pack4h(src[i]);
}

// Load A-stage registers for K-tile f (16 halves per thread).
// CVTA: A is fp32 (x/h) -> load 4x float4 and convert. Else fp16 (g_hr16).
template <bool CVTA>
__device__ __forceinline__ void ldgA(
    uint32_t (&ast)[8], const void* Alo, const void* Ahi, int f, int row, int segh)
{
    if (CVTA) {
        const float* A = (const float*)((f < 32) ? Alo : Ahi);
        const float4* p = (const float4*)(A + (size_t)row * HSZ + (f & 31) * 32 + segh);
        float4 v0 = p[0], v1 = p[1], v2 = p[2], v3 = p[3];
        uint2 a = pack4h(v0), b = pack4h(v1), c = pack4h(v2), d = pack4h(v3);
        ast[0] = a.x; ast[1] = a.y; ast[2] = b.x; ast[3] = b.y;
        ast[4] = c.x; ast[5] = c.y; ast[6] = d.x; ast[7] = d.y;
    } else {
        const __half* A = (const __half*)((f < 32) ? Alo : Ahi);
        const uint4* p = (const uint4*)(A + (size_t)row * HSZ + (f & 31) * 32 + segh);
        uint4 v0 = p[0], v1 = p[1];
        ast[0] = v0.x; ast[1] = v0.y; ast[2] = v0.z; ast[3] = v0.w;
        ast[4] = v1.x; ast[5] = v1.y; ast[6] = v1.z; ast[7] = v1.w;
    }
}

// Pipelined mainloop: A global->reg->smem (one-iteration cover), B cp.async,
// NST stages, ONE __syncthreads per K-tile, A-frags double-buffered in-tile.
// Warp tile 64x32: ms=4 (16-row steps), ns=4 (8-col steps). acc[4][4][4].
template <bool CVTA>
__device__ __forceinline__ void gemm_main(
    char* sm, float (&acc)[4][4][4],
    const void* Alo, const void* Ahi, const __half* Blo, const __half* Bhi,
    int KT, int tid, int wm, int wn, int lane)
{
#pragma unroll
    for (int i = 0; i < 4; ++i)
#pragma unroll
        for (int j = 0; j < 4; ++j)
#pragma unroll
            for (int k = 0; k < 4; ++k) acc[i][j][k] = 0.0f;

    int row = tid >> 1;                 // 0..127
    int segh = (tid & 1) * 16;          // halves
    uint32_t a_sm_off = (uint32_t)(row * (APADH * 2) + (tid & 1) * 32);
    size_t b_g_off = (size_t)row * (HSZ * 2) + (tid & 1) * 32;   // bytes

    // ldmatrix per-thread base offsets (in halves, relative to stage base)
    int q = lane >> 3, r8 = lane & 7;
    int aoff = (wm + (q & 1) * 8 + r8) * APADH + (q >> 1) * 8;
    int boff = A_HALVES + (wn + (q >> 1) * 8 + r8) * APADH + (q & 1) * 8;

    uint32_t smbase = (uint32_t)__cvta_generic_to_shared(sm);

    uint32_t ast[8];
    ldgA<CVTA>(ast, Alo, Ahi, 0, row, segh);

#pragma unroll
    for (int f = 0; f < NST - 1; ++f) {
        char* st = sm + (size_t)f * STAGE_BYTES;
        *(uint4*)(st + a_sm_off) = *(uint4*)&ast[0];
        *(uint4*)(st + a_sm_off + 16) = *(uint4*)&ast[4];
        const __half* Bk = (f < 32) ? Blo + (size_t)(f & 31) * BK
                                    : Bhi + (size_t)(f - 32) * BK;
        char* Bs = st + A_HALVES * 2;
        cp16(Bs + a_sm_off, (const char*)Bk + b_g_off);
        cp16(Bs + a_sm_off + 16, (const char*)Bk + b_g_off + 16);
        cp_commit();
        ldgA<CVTA>(ast, Alo, Ahi, f + 1, row, segh);
    }

    for (int kt = 0; kt < KT; ++kt) {
        cp_wait(min(NST - 2, KT - 1 - kt));
        __syncthreads();

        int nf = kt + NST - 1;
        if (nf < KT) {
            char* st = sm + (size_t)(nf % NST) * STAGE_BYTES;
            *(uint4*)(st + a_sm_off) = *(uint4*)&ast[0];
            *(uint4*)(st + a_sm_off + 16) = *(uint4*)&ast[4];
            const __half* Bk = (nf < 32) ? Blo + (size_t)(nf & 31) * BK
                                         : Bhi + (size_t)(nf - 32) * BK;
            char* Bs = st + A_HALVES * 2;
            cp16(Bs + a_sm_off, (const char*)Bk + b_g_off);
            cp16(Bs + a_sm_off + 16, (const char*)Bk + b_g_off + 16);
            cp_commit();
        }
        if (nf + 1 < KT)
            ldgA<CVTA>(ast, Alo, Ahi, nf + 1, row, segh);

        uint32_t stg = smbase + (uint32_t)((kt % NST) * STAGE_BYTES);

        uint32_t aP[4][4], aQ[4][4];
#pragma unroll
        for (int ms = 0; ms < 4; ++ms)
            ldsm4(aP[ms][0], aP[ms][1], aP[ms][2], aP[ms][3],
                  stg + 2 * (uint32_t)(aoff + ms * 16 * APADH));
#pragma unroll
        for (int kk = 0; kk < 2; ++kk) {
            uint32_t (&aC)[4][4] = (kk & 1) ? aQ : aP;
            if (kk == 0) {
#pragma unroll
                for (int ms = 0; ms < 4; ++ms)
                    ldsm4(aQ[ms][0], aQ[ms][1], aQ[ms][2], aQ[ms][3],
                          stg + 2 * (uint32_t)(aoff + ms * 16 * APADH + 16));
            }
            uint32_t b[4][2];
#pragma unroll
            for (int pp = 0; pp < 2; ++pp)
                ldsm4(b[2 * pp][0], b[2 * pp][1], b[2 * pp + 1][0], b[2 * pp + 1][1],
                      stg + 2 * (uint32_t)(boff + pp * 16 * APADH + kk * 16));
#pragma unroll
            for (int ns = 0; ns < 4; ++ns)
#pragma unroll
                for (int ms = 0; ms < 4; ++ms)
                    mma_f16(acc[ms][ns], aC[ms], b[ns][0], b[ns][1]);
        }
    }
}

// ---------------- fused kernel: gates r,u,c (z=0..2) + final pass (z=3) ----
__global__ void __launch_bounds__(NTHREADS, 2) gru_all(
    const float* __restrict__ x, const float* __restrict__ h,
    const float* __restrict__ bWr, const float* __restrict__ bUr,
    const float* __restrict__ bWu, const float* __restrict__ bUu,
    const float* __restrict__ bW, const float* __restrict__ bU,
    float* __restrict__ out)
{
    extern __shared__ char sm[];
    int tid = threadIdx.x, wid = tid >> 5, lane = tid & 31;
    int g = lane >> 2, t = lane & 3;
    int wm = (wid & 1) * 64, wn = (wid >> 1) * 32;
    int gate = blockIdx.z;
    int m0 = blockIdx.y * BM, n0 = blockIdx.x * BN;

    if (gate < 3) {
        int KT = (gate == 2) ? 32 : 64;
        const __half *Blo, *Bhi;
        const float *b1, *b2;
        if (gate == 0)      { Blo = g_w16[0]; Bhi = g_w16[1]; b1 = bWr; b2 = bUr; }
        else if (gate == 1) { Blo = g_w16[2]; Bhi = g_w16[3]; b1 = bWu; b2 = bUu; }
        else                { Blo = g_w16[4]; Bhi = g_w16[4]; b1 = bW;  b2 = bU;  }

        float* bias = (float*)(sm + BIAS_BYTE_OFF);
        if (tid < BN) bias[tid] = b1[n0 + tid] + b2[n0 + tid];

        float acc[4][4][4];
        gemm_main<true>(sm, acc,
                  x + (size_t)m0 * HSZ, h + (size_t)m0 * HSZ,
                  Blo + (size_t)n0 * HSZ, Bhi + (size_t)n0 * HSZ,
                  KT, tid, wm, wn, lane);

#pragma unroll
        for (int ms = 0; ms < 4; ++ms) {
#pragma unroll
            for (int half = 0; half < 2; ++half) {
                size_t row = (size_t)(m0 + wm + ms * 16 + g + half * 8);
#pragma unroll
                for (int ns = 0; ns < 4; ++ns) {
                    int col = wn + ns * 8 + 2 * t;
                    float v0 = acc[ms][ns][half * 2 + 0] + bias[col + 0];
                    float v1 = acc[ms][ns][half * 2 + 1] + bias[col + 1];
                    size_t idx = row * HSZ + n0 + col;
                    if (gate == 0) {
                        float2 hv = *(const float2*)(h + idx);
                        *(__half2*)(g_hr16 + idx) =
                            __floats2half2_rn(hv.x * sigmf(v0), hv.y * sigmf(v1));
                    } else if (gate == 1) {
                        *(__half2*)(g_u16 + idx) = __floats2half2_rn(sigmf(v0), sigmf(v1));
                    } else {
                        *(__half2*)(g_gc16 + idx) = __floats2half2_rn(v0, v1);
                    }
                }
            }
        }
        __threadfence();
        __syncthreads();
        if (tid == 0) {
            if (gate == 0) atomicAdd(&g_ready0[blockIdx.y], 1);
            else           atomicAdd(&g_ready12[blockIdx.y], 1);
        }
    } else {
        // z=3: (h*r)@U^T + final combine. Wait for gate-0 rows first.
        if (tid == 0) {
            int c = 0;
            while (atomicAdd(&g_ready0[blockIdx.y], 0) < 8) {
                if (++c > (1 << 22)) break;   // bounded: never hang the chip
            }
        }
        __syncthreads();
        __threadfence();

        float acc[4][4][4];
        gemm_main<false>(sm, acc,
                  g_hr16 + (size_t)m0 * HSZ, g_hr16 + (size_t)m0 * HSZ,
                  g_w16[5] + (size_t)n0 * HSZ, g_w16[5] + (size_t)n0 * HSZ,
                  32, tid, wm, wn, lane);

        if (tid == 0) {
            int c = 0;
            while (atomicAdd(&g_ready12[blockIdx.y], 0) < 16) {
                if (++c > (1 << 22)) break;
            }
        }
        __syncthreads();
        __threadfence();

#pragma unroll
        for (int ms = 0; ms < 4; ++ms) {
#pragma unroll
            for (int half = 0; half < 2; ++half) {
                size_t row = (size_t)(m0 + wm + ms * 16 + g + half * 8);
#pragma unroll
                for (int ns = 0; ns < 4; ++ns) {
                    int col = wn + ns * 8 + 2 * t;
                    size_t idx = row * HSZ + n0 + col;
                    uint32_t gcu = __ldcg((const unsigned int*)(g_gc16 + idx));
                    uint32_t uuu = __ldcg((const unsigned int*)(g_u16 + idx));
                    float2 gc = __half22float2(*(__half2*)&gcu);
                    float2 uu = __half22float2(*(__half2*)&uuu);
                    float2 hv = *(const float2*)(h + idx);
                    float c0 = tanhfast(acc[ms][ns][half * 2 + 0] + gc.x);
                    float c1 = tanhfast(acc[ms][ns][half * 2 + 1] + gc.y);
                    float2 o;
                    o.x = hv.x + uu.x * (c0 - hv.x);
                    o.y = hv.y + uu.y * (c1 - hv.y);
                    *(float2*)(out + idx) = o;
                }
            }
        }
    }
}

// ---------------- host ----------------
extern "C" void kernel_launch(void* const* d_in, const int* in_sizes, int n_in,
                              void* d_out, int out_size) {
    (void)in_sizes; (void)n_in; (void)out_size;
    const float* x   = (const float*)d_in[0];
    const float* h   = (const float*)d_in[1];
    const float* Wr  = (const float*)d_in[2];
    const float* bWr = (const float*)d_in[3];
    const float* Ur  = (const float*)d_in[4];
    const float* bUr = (const float*)d_in[5];
    const float* Wu  = (const float*)d_in[6];
    const float* bWu = (const float*)d_in[7];
    const float* Uu  = (const float*)d_in[8];
    const float* bUu = (const float*)d_in[9];
    const float* W   = (const float*)d_in[10];
    const float* bW  = (const float*)d_in[11];
    const float* U   = (const float*)d_in[12];
    const float* bU  = (const float*)d_in[13];

    cudaFuncSetAttribute(gru_all, cudaFuncAttributeMaxDynamicSharedMemorySize, SMEM_BYTES);

    cvt_w6<<<dim3(256, 6), 256>>>((const float4*)Wr, (const float4*)Ur,
                                  (const float4*)Wu, (const float4*)Uu,
                                  (const float4*)W,  (const float4*)U);

    gru_all<<<dim3(HSZ / BN, BSZ / BM, 4), NTHREADS, SMEM_BYTES>>>(
        x, h, bWr, bUr, bWu, bUu, bW, bU, (float*)d_out);
}

// round 17
// speedup vs baseline: 1.6010x; 1.6010x over previous
#include <cuda_runtime.h>
#include <cuda_fp16.h>
#include <cstdint>
#include <cstddef>

#define BSZ 16384
#define HSZ 1024

#define BM 128
#define BN 128
#define BK 32                         /* halves of K per tile */
#define NST 5
#define APADH 40                      /* halves per smem row = 80 B */
#define A_HALVES (BM * APADH)         /* 5120 */
#define B_HALVES (BN * APADH)         /* 5120 */
#define STAGE_HALVES (A_HALVES + B_HALVES)      /* 10240 -> 20480 B */
#define STAGE_BYTES (STAGE_HALVES * 2)
#define BIAS_BYTE_OFF (NST * STAGE_BYTES)       /* 102400 */
#define SMEM_BYTES (BIAS_BYTE_OFF + BN * 4)     /* 102912, x2 CTA = 205824 */

#define NTHREADS 256                  /* 8 warps, 64x32 warp tiles, 2 CTAs/SM */

// fp16 operand scratch + fp16 epilogue scratch
__device__ __align__(16) __half g_x16[(size_t)BSZ * HSZ];
__device__ __align__(16) __half g_h16[(size_t)BSZ * HSZ];
__device__ __align__(16) __half g_hr16[(size_t)BSZ * HSZ];    // h*r (fp16)
__device__ __align__(16) __half g_u16[(size_t)BSZ * HSZ];     // update gate (fp16)
__device__ __align__(16) __half g_gc16[(size_t)BSZ * HSZ];    // x@W^T + biases (fp16)
__device__ __align__(16) __half g_w16[6][(size_t)HSZ * HSZ];  // Wr,Ur,Wu,Uu,W,U

// readiness counters per m-block (128 blocks of 128 rows)
__device__ int g_ready0[BSZ / BM];    // gate-0 tiles stored (target 8)
__device__ int g_ready12[BSZ / BM];   // gate-1/2 tiles stored (target 16)

// ---------------- helpers (base-ISA only) ----------------
__device__ __forceinline__ void cp16(void* dst_smem, const void* src) {
    uint32_t d = (uint32_t)__cvta_generic_to_shared(dst_smem);
    asm volatile("cp.async.cg.shared.global [%0], [%1], 16;" :: "r"(d), "l"(src));
}
__device__ __forceinline__ void cp_commit() {
    asm volatile("cp.async.commit_group;" ::: "memory");
}
__device__ __forceinline__ void cp_wait(int pending) {
    if (pending >= 2)      asm volatile("cp.async.wait_group 2;" ::: "memory");
    else if (pending == 1) asm volatile("cp.async.wait_group 1;" ::: "memory");
    else                   asm volatile("cp.async.wait_group 0;" ::: "memory");
}
__device__ __forceinline__ void mma_f16(float* c, const uint32_t* a, uint32_t b0, uint32_t b1) {
    asm volatile(
        "mma.sync.aligned.m16n8k16.row.col.f32.f16.f16.f32 "
        "{%0,%1,%2,%3}, {%4,%5,%6,%7}, {%8,%9}, {%0,%1,%2,%3};"
        : "+f"(c[0]), "+f"(c[1]), "+f"(c[2]), "+f"(c[3])
        : "r"(a[0]), "r"(a[1]), "r"(a[2]), "r"(a[3]), "r"(b0), "r"(b1));
}
__device__ __forceinline__ void ldsm4(uint32_t& r0, uint32_t& r1, uint32_t& r2, uint32_t& r3,
                                      uint32_t addr) {
    asm volatile("ldmatrix.sync.aligned.m8n8.x4.shared.b16 {%0,%1,%2,%3}, [%4];"
        : "=r"(r0), "=r"(r1), "=r"(r2), "=r"(r3) : "r"(addr));
}
__device__ __forceinline__ float sigmf(float x) { return 1.0f / (1.0f + __expf(-x)); }
__device__ __forceinline__ float tanhfast(float x) { return 2.0f / (1.0f + __expf(-2.0f * x)) - 1.0f; }

__device__ __forceinline__ uint2 pack4h(float4 v) {
    __half2 lo = __floats2half2_rn(v.x, v.y);
    __half2 hi = __floats2half2_rn(v.z, v.w);
    uint2 o;
    o.x = *(uint32_t*)&lo;
    o.y = *(uint32_t*)&hi;
    return o;
}

// ---------------- single fp16 pre-convert launch: 6 weights + x + h -------
// blockIdx.y: 0..5 -> weight matrices (1M elems each), 6 -> x, 7 -> h (16M).
__global__ void __launch_bounds__(256) cvt_all(
    const float4* __restrict__ x, const float4* __restrict__ h,
    const float4* __restrict__ s0, const float4* __restrict__ s1,
    const float4* __restrict__ s2, const float4* __restrict__ s3,
    const float4* __restrict__ s4, const float4* __restrict__ s5)
{
    if (blockIdx.x == 0 && blockIdx.y == 0 && threadIdx.x < BSZ / BM) {
        g_ready0[threadIdx.x] = 0;
        g_ready12[threadIdx.x] = 0;
    }
    int seg = blockIdx.y;
    const float4* src;
    uint2* dst;
    int n4;
    if (seg < 6) {
        n4 = (HSZ * HSZ) / 4;
        src = (seg == 0) ? s0 : (seg == 1) ? s1 : (seg == 2) ? s2
            : (seg == 3) ? s3 : (seg == 4) ? s4 : s5;
        dst = (uint2*)g_w16 + (size_t)seg * n4;
    } else {
        n4 = (BSZ * HSZ) / 4;
        src = (seg == 6) ? x : h;
        dst = (seg == 6) ? (uint2*)g_x16 : (uint2*)g_h16;
    }
    int i = blockIdx.x * 256 + threadIdx.x;
    int stride = gridDim.x * 256;
    for (; i + stride < n4; i += 2 * stride) {
        float4 a = src[i];
        float4 b = src[i + stride];
        dst[i] = pack4h(a);
        dst[i + stride] = pack4h(b);
    }
    if (i < n4) dst[i] = pack4h(src[i]);
}

// Issue one K-tile stage: A 128x32 halves, B 128x32 halves (64 B rows).
__device__ __forceinline__ void issue_stage(
    char* sm, int s, const __half* Ak, const __half* Bk, int tid)
{
    char* As = sm + (size_t)s * STAGE_BYTES;
    char* Bs = As + A_HALVES * 2;
    int r = tid >> 2, cb = (tid & 3) * 16;   // r: 0..63, cb: byte offset in row
#pragma unroll
    for (int i = 0; i < 2; ++i) {
        int row = r + i * 64;
        cp16(As + row * (APADH * 2) + cb, (const char*)Ak + (size_t)row * (HSZ * 2) + cb);
        cp16(Bs + row * (APADH * 2) + cb, (const char*)Bk + (size_t)row * (HSZ * 2) + cb);
    }
    cp_commit();
}

// Pipelined mainloop (R13/R15, proven): NST cp.async stages, ONE
// __syncthreads per K-tile, fragments software-pipelined across K-tiles.
// Warp tile 64x32: ms=4 (16-row steps), ns=4 (8-col steps). acc[4][4][4].
__device__ __forceinline__ void gemm_main(
    char* sm, float (&acc)[4][4][4],
    const __half* Alo, const __half* Ahi, const __half* Blo, const __half* Bhi,
    int KT, int tid, int wm, int wn, int lane)
{
#pragma unroll
    for (int i = 0; i < 4; ++i)
#pragma unroll
        for (int j = 0; j < 4; ++j)
#pragma unroll
            for (int k = 0; k < 4; ++k) acc[i][j][k] = 0.0f;

    // ldmatrix per-thread base offsets (in halves, relative to stage base)
    int q = lane >> 3, r8 = lane & 7;
    int aoff = (wm + (q & 1) * 8 + r8) * APADH + (q >> 1) * 8;
    int boff = A_HALVES + (wn + (q >> 1) * 8 + r8) * APADH + (q & 1) * 8;

    uint32_t smbase = (uint32_t)__cvta_generic_to_shared(sm);

#pragma unroll
    for (int f = 0; f < NST - 1; ++f) {
        if (f < KT) {
            const __half* Ak = (f < 32) ? Alo + f * BK : Ahi + (f - 32) * BK;
            const __half* Bk = (f < 32) ? Blo + f * BK : Bhi + (f - 32) * BK;
            issue_stage(sm, f, Ak, Bk, tid);
        }
    }

    uint32_t aP[4][4], aQ[4][4], bP[4][2], bQ[4][2];

    for (int kt = 0; kt < KT; ++kt) {
        int p = KT - 2 - kt;
        p = (p < 0) ? 0 : (p > 2 ? 2 : p);
        cp_wait(p);
        __syncthreads();

        uint32_t stg = smbase + (uint32_t)((kt % NST) * STAGE_BYTES);

        if (kt == 0) {
#pragma unroll
            for (int ms = 0; ms < 4; ++ms)
                ldsm4(aP[ms][0], aP[ms][1], aP[ms][2], aP[ms][3],
                      stg + 2 * (uint32_t)(aoff + ms * 16 * APADH));
#pragma unroll
            for (int pp = 0; pp < 2; ++pp)
                ldsm4(bP[2 * pp][0], bP[2 * pp][1], bP[2 * pp + 1][0], bP[2 * pp + 1][1],
                      stg + 2 * (uint32_t)(boff + pp * 16 * APADH));
        }

        // prefetch kk1 fragments of current tile
#pragma unroll
        for (int ms = 0; ms < 4; ++ms)
            ldsm4(aQ[ms][0], aQ[ms][1], aQ[ms][2], aQ[ms][3],
                  stg + 2 * (uint32_t)(aoff + ms * 16 * APADH + 16));
#pragma unroll
        for (int pp = 0; pp < 2; ++pp)
            ldsm4(bQ[2 * pp][0], bQ[2 * pp][1], bQ[2 * pp + 1][0], bQ[2 * pp + 1][1],
                  stg + 2 * (uint32_t)(boff + pp * 16 * APADH + 16));

        // MMA kk0
#pragma unroll
        for (int ns = 0; ns < 4; ++ns)
#pragma unroll
            for (int ms = 0; ms < 4; ++ms)
                mma_f16(acc[ms][ns], aP[ms], bP[ns][0], bP[ns][1]);

        // prefetch kk0 fragments of NEXT tile (stage kt+1 complete + published)
        if (kt + 1 < KT) {
            uint32_t stg2 = smbase + (uint32_t)(((kt + 1) % NST) * STAGE_BYTES);
#pragma unroll
            for (int ms = 0; ms < 4; ++ms)
                ldsm4(aP[ms][0], aP[ms][1], aP[ms][2], aP[ms][3],
                      stg2 + 2 * (uint32_t)(aoff + ms * 16 * APADH));
#pragma unroll
            for (int pp = 0; pp < 2; ++pp)
                ldsm4(bP[2 * pp][0], bP[2 * pp][1], bP[2 * pp + 1][0], bP[2 * pp + 1][1],
                      stg2 + 2 * (uint32_t)(boff + pp * 16 * APADH));
        }

        // MMA kk1
#pragma unroll
        for (int ns = 0; ns < 4; ++ns)
#pragma unroll
            for (int ms = 0; ms < 4; ++ms)
                mma_f16(acc[ms][ns], aQ[ms], bQ[ns][0], bQ[ns][1]);

        int nf = kt + NST - 1;
        if (nf < KT) {
            const __half* Ak = (nf < 32) ? Alo + nf * BK : Ahi + (nf - 32) * BK;
            const __half* Bk = (nf < 32) ? Blo + nf * BK : Bhi + (nf - 32) * BK;
            issue_stage(sm, nf % NST, Ak, Bk, tid);
        }
    }
}

// ---------------- fused kernel: gates r,u,c (z=0..2) + final pass (z=3) ----
__global__ void __launch_bounds__(NTHREADS, 2) gru_all(
    const float* __restrict__ h,
    const float* __restrict__ bWr, const float* __restrict__ bUr,
    const float* __restrict__ bWu, const float* __restrict__ bUu,
    const float* __restrict__ bW, const float* __restrict__ bU,
    float* __restrict__ out)
{
    extern __shared__ char sm[];
    int tid = threadIdx.x, wid = tid >> 5, lane = tid & 31;
    int g = lane >> 2, t = lane & 3;
    int wm = (wid & 1) * 64, wn = (wid >> 1) * 32;
    int gate = blockIdx.z;
    int m0 = blockIdx.y * BM, n0 = blockIdx.x * BN;

    if (gate < 3) {
        int KT = (gate == 2) ? 32 : 64;
        const __half *Blo, *Bhi;
        const float *b1, *b2;
        if (gate == 0)      { Blo = g_w16[0]; Bhi = g_w16[1]; b1 = bWr; b2 = bUr; }
        else if (gate == 1) { Blo = g_w16[2]; Bhi = g_w16[3]; b1 = bWu; b2 = bUu; }
        else                { Blo = g_w16[4]; Bhi = g_w16[4]; b1 = bW;  b2 = bU;  }

        float* bias = (float*)(sm + BIAS_BYTE_OFF);
        if (tid < BN) bias[tid] = b1[n0 + tid] + b2[n0 + tid];

        float acc[4][4][4];
        gemm_main(sm, acc,
                  g_x16 + (size_t)m0 * HSZ, g_h16 + (size_t)m0 * HSZ,
                  Blo + (size_t)n0 * HSZ, Bhi + (size_t)n0 * HSZ,
                  KT, tid, wm, wn, lane);

#pragma unroll
        for (int ms = 0; ms < 4; ++ms) {
#pragma unroll
            for (int half = 0; half < 2; ++half) {
                size_t row = (size_t)(m0 + wm + ms * 16 + g + half * 8);
#pragma unroll
                for (int ns = 0; ns < 4; ++ns) {
                    int col = wn + ns * 8 + 2 * t;
                    float v0 = acc[ms][ns][half * 2 + 0] + bias[col + 0];
                    float v1 = acc[ms][ns][half * 2 + 1] + bias[col + 1];
                    size_t idx = row * HSZ + n0 + col;
                    if (gate == 0) {
                        __half2 hh = *(const __half2*)(g_h16 + idx);
                        float2 hv = __half22float2(hh);
                        *(__half2*)(g_hr16 + idx) =
                            __floats2half2_rn(hv.x * sigmf(v0), hv.y * sigmf(v1));
                    } else if (gate == 1) {
                        *(__half2*)(g_u16 + idx) = __floats2half2_rn(sigmf(v0), sigmf(v1));
                    } else {
                        *(__half2*)(g_gc16 + idx) = __floats2half2_rn(v0, v1);
                    }
                }
            }
        }
        __threadfence();
        __syncthreads();
        if (tid == 0) {
            if (gate == 0) atomicAdd(&g_ready0[blockIdx.y], 1);
            else           atomicAdd(&g_ready12[blockIdx.y], 1);
        }
    } else {
        // z=3: (h*r)@U^T + final combine. Wait for gate-0 rows first.
        if (tid == 0) {
            int c = 0;
            while (atomicAdd(&g_ready0[blockIdx.y], 0) < 8) {
                if (++c > (1 << 22)) break;   // bounded: never hang the chip
            }
        }
        __syncthreads();
        __threadfence();

        float acc[4][4][4];
        gemm_main(sm, acc,
                  g_hr16 + (size_t)m0 * HSZ, g_hr16 + (size_t)m0 * HSZ,
                  g_w16[5] + (size_t)n0 * HSZ, g_w16[5] + (size_t)n0 * HSZ,
                  32, tid, wm, wn, lane);

        if (tid == 0) {
            int c = 0;
            while (atomicAdd(&g_ready12[blockIdx.y], 0) < 16) {
                if (++c > (1 << 22)) break;
            }
        }
        __syncthreads();
        __threadfence();

#pragma unroll
        for (int ms = 0; ms < 4; ++ms) {
#pragma unroll
            for (int half = 0; half < 2; ++half) {
                size_t row = (size_t)(m0 + wm + ms * 16 + g + half * 8);
#pragma unroll
                for (int ns = 0; ns < 4; ++ns) {
                    int col = wn + ns * 8 + 2 * t;
                    size_t idx = row * HSZ + n0 + col;
                    uint32_t gcu = __ldcg((const unsigned int*)(g_gc16 + idx));
                    uint32_t uuu = __ldcg((const unsigned int*)(g_u16 + idx));
                    float2 gc = __half22float2(*(__half2*)&gcu);
                    float2 uu = __half22float2(*(__half2*)&uuu);
                    float2 hv = *(const float2*)(h + idx);
                    float c0 = tanhfast(acc[ms][ns][half * 2 + 0] + gc.x);
                    float c1 = tanhfast(acc[ms][ns][half * 2 + 1] + gc.y);
                    float2 o;
                    o.x = hv.x + uu.x * (c0 - hv.x);
                    o.y = hv.y + uu.y * (c1 - hv.y);
                    *(float2*)(out + idx) = o;
                }
            }
        }
    }
}

// ---------------- host ----------------
extern "C" void kernel_launch(void* const* d_in, const int* in_sizes, int n_in,
                              void* d_out, int out_size) {
    (void)in_sizes; (void)n_in; (void)out_size;
    const float* x   = (const float*)d_in[0];
    const float* h   = (const float*)d_in[1];
    const float* Wr  = (const float*)d_in[2];
    const float* bWr = (const float*)d_in[3];
    const float* Ur  = (const float*)d_in[4];
    const float* bUr = (const float*)d_in[5];
    const float* Wu  = (const float*)d_in[6];
    const float* bWu = (const float*)d_in[7];
    const float* Uu  = (const float*)d_in[8];
    const float* bUu = (const float*)d_in[9];
    const float* W   = (const float*)d_in[10];
    const float* bW  = (const float*)d_in[11];
    const float* U   = (const float*)d_in[12];
    const float* bU  = (const float*)d_in[13];

    cudaFuncSetAttribute(gru_all, cudaFuncAttributeMaxDynamicSharedMemorySize, SMEM_BYTES);

    cvt_all<<<dim3(1024, 8), 256>>>((const float4*)x, (const float4*)h,
                                    (const float4*)Wr, (const float4*)Ur,
                                    (const float4*)Wu, (const float4*)Uu,
                                    (const float4*)W,  (const float4*)U);

    gru_all<<<dim3(HSZ / BN, BSZ / BM, 4), NTHREADS, SMEM_BYTES>>>(
        h, bWr, bUr, bWu, bUu, bW, bU, (float*)d_out);
}